// round 2
// baseline (speedup 1.0000x reference)
#include <cuda_runtime.h>
#include <math.h>

#define L 256
#define D 1024
#define H 16
#define DH 64

// ---------------- device scratch (no allocations allowed) ----------------
__device__ float g_Qm[L*D], g_Qv[L*D], g_Km[L*D], g_Kv[L*D], g_Vm[L*D], g_Vv[L*D];
__device__ float g_A [L*D];   // 0.5*(Qm^2 + Qv)
__device__ float g_F1[L*D];   // 1/Kv
__device__ float g_F2[L*D];   // Km/Kv
__device__ float g_Ck[H*L];   // per-(head,k) bias: sum_d 0.5*(Km^2/Kv + log Kv)
__device__ float g_Om[L*D], g_Ov[L*D];

// ---------------- f32x2 packed FMA helpers (sm_100+) ----------------
__device__ __forceinline__ unsigned long long pack2(float lo, float hi) {
    unsigned long long r;
    asm("mov.b64 %0, {%1, %2};" : "=l"(r) : "f"(lo), "f"(hi));
    return r;
}
__device__ __forceinline__ void unpack2(unsigned long long v, float& lo, float& hi) {
    asm("mov.b64 {%0, %1}, %2;" : "=f"(lo), "=f"(hi) : "l"(v));
}
__device__ __forceinline__ unsigned long long fma2(unsigned long long a,
                                                   unsigned long long b,
                                                   unsigned long long c) {
    unsigned long long d;
    asm("fma.rn.f32x2 %0, %1, %2, %3;" : "=l"(d) : "l"(a), "l"(b), "l"(c));
    return d;
}

__device__ __forceinline__ float softplusf(float x) {
    // logaddexp(x, 0) — overflow-safe, matches jax.nn.softplus
    return fmaxf(x, 0.0f) + log1pf(expf(-fabsf(x)));
}

// ---------------- 128x128 fp32 GEMM tile, f32x2 inner product ----------------
// C[row, col] = sum_k A[row,k] * W[k,col] + bias[col]   (M=256, N=K=D=1024)
__device__ __forceinline__ void sgemm_tile(
    const float* __restrict__ Am, const float* __restrict__ W,
    const float* __restrict__ bias, float* __restrict__ C,
    int bm, int bn, bool sp)
{
    __shared__ float As[2][16][132];  // [k][m], padded
    __shared__ float Bs[2][16][128];  // [k][n]
    const int tid = threadIdx.x;
    const int tx  = tid & 15, ty = tid >> 4;

    unsigned long long acc[8][4];
    #pragma unroll
    for (int i = 0; i < 8; i++)
        #pragma unroll
        for (int j = 0; j < 4; j++) acc[i][j] = 0ull;

    float4 ar[2], br[2];
    auto LDG = [&](int kt) {
        #pragma unroll
        for (int u = 0; u < 2; u++) {
            int idx  = tid + u * 256;
            int arow = idx >> 2, ak = (idx & 3) << 2;
            ar[u] = *(const float4*)(Am + (bm + arow) * D + kt + ak);
            int brow = idx >> 5, bc = (idx & 31) << 2;
            br[u] = *(const float4*)(W + (kt + brow) * D + bn + bc);
        }
    };
    auto STS = [&](int buf) {
        #pragma unroll
        for (int u = 0; u < 2; u++) {
            int idx  = tid + u * 256;
            int arow = idx >> 2, ak = (idx & 3) << 2;
            As[buf][ak + 0][arow] = ar[u].x;
            As[buf][ak + 1][arow] = ar[u].y;
            As[buf][ak + 2][arow] = ar[u].z;
            As[buf][ak + 3][arow] = ar[u].w;
            int brow = idx >> 5, bc = (idx & 31) << 2;
            *(float4*)&Bs[buf][brow][bc] = br[u];
        }
    };

    LDG(0); STS(0); __syncthreads();
    const int NK = D / 16;
    for (int t = 0; t < NK; t++) {
        int cur = t & 1;
        if (t + 1 < NK) LDG((t + 1) * 16);
        #pragma unroll
        for (int k = 0; k < 16; k++) {
            float4 aL = *(const float4*)&As[cur][k][ty * 4];
            float4 aH = *(const float4*)&As[cur][k][64 + ty * 4];
            float4 bL = *(const float4*)&Bs[cur][k][tx * 4];
            float4 bH = *(const float4*)&Bs[cur][k][64 + tx * 4];
            unsigned long long b2[4] = { pack2(bL.x, bL.y), pack2(bL.z, bL.w),
                                         pack2(bH.x, bH.y), pack2(bH.z, bH.w) };
            float av[8] = { aL.x, aL.y, aL.z, aL.w, aH.x, aH.y, aH.z, aH.w };
            #pragma unroll
            for (int i = 0; i < 8; i++) {
                unsigned long long a2 = pack2(av[i], av[i]);
                #pragma unroll
                for (int j = 0; j < 4; j++) acc[i][j] = fma2(a2, b2[j], acc[i][j]);
            }
        }
        if (t + 1 < NK) STS(cur ^ 1);
        __syncthreads();
    }

    #pragma unroll
    for (int i = 0; i < 8; i++) {
        int row = bm + ((i < 4) ? (ty * 4 + i) : (64 + ty * 4 + (i - 4)));
        #pragma unroll
        for (int j = 0; j < 4; j++) {
            int col = bn + ((j < 2) ? (tx * 4 + j * 2) : (64 + tx * 4 + (j - 2) * 2));
            float lo, hi; unpack2(acc[i][j], lo, hi);
            lo += bias[col]; hi += bias[col + 1];
            if (sp) { lo = softplusf(lo); hi = softplusf(hi); }
            *(float2*)(C + row * D + col) = make_float2(lo, hi);
        }
    }
}

// ---------------- kernel 1: six QKV GEMMs ----------------
__global__ __launch_bounds__(256) void qkv_gemm_kernel(
    const float* mu, const float* var,
    const float* wqm, const float* bqm, const float* wqv, const float* bqv,
    const float* wkm, const float* bkm, const float* wkv, const float* bkv,
    const float* wvm, const float* bvm, const float* wvv, const float* bvv)
{
    const float* A; const float* W; const float* b; float* C; bool sp;
    switch (blockIdx.z) {
        case 0:  A = mu;  W = wqm; b = bqm; C = g_Qm; sp = false; break;
        case 1:  A = var; W = wqv; b = bqv; C = g_Qv; sp = true;  break;
        case 2:  A = mu;  W = wkm; b = bkm; C = g_Km; sp = false; break;
        case 3:  A = var; W = wkv; b = bkv; C = g_Kv; sp = true;  break;
        case 4:  A = mu;  W = wvm; b = bvm; C = g_Vm; sp = false; break;
        default: A = var; W = wvv; b = bvv; C = g_Vv; sp = true;  break;
    }
    sgemm_tile(A, W, b, C, blockIdx.y * 128, blockIdx.x * 128, sp);
}

// ---------------- kernel 2: elementwise features + per-k bias ----------------
__global__ __launch_bounds__(256) void prep_kernel()
{
    int tid = blockIdx.x * 256 + threadIdx.x;   // 0..131071, 2 elems each
    int e0  = tid * 2;
    float c = 0.0f;
    #pragma unroll
    for (int u = 0; u < 2; u++) {
        int e = e0 + u;
        float qm = g_Qm[e], qv = g_Qv[e];
        g_A[e] = 0.5f * (qm * qm + qv);
        float kv  = g_Kv[e];
        float inv = 1.0f / kv;
        float km  = g_Km[e];
        g_F1[e] = inv;
        g_F2[e] = km * inv;
        c += 0.5f * (km * km * inv + logf(kv));
    }
    // one warp == one (row, head) group of 64 elements
    #pragma unroll
    for (int off = 16; off; off >>= 1) c += __shfl_xor_sync(0xffffffffu, c, off);
    if ((threadIdx.x & 31) == 0) {
        int w = tid >> 5;
        int row = w >> 4, h = w & 15;
        g_Ck[h * L + row] = c;
    }
}

// ---------------- kernel 3: fused attention per (q-tile-64, head) ----------------
// smem layout (floats):
//   phase 1: sAq[64][65] @0, sQm[64][65] @4160, sF1t[64][257] @8320,
//            sF2t[64][257] @24768, sCk[256] @41216
//   phase 2: sVm[64][64] @0, sVv[64][64] @4096, sP[256][65] @8320, sP2[256][65] @24960
#define ATTN_SMEM_FLOATS 41600
#define O_AQ 0
#define O_QM 4160
#define O_F1 8320
#define O_F2 24768
#define O_CK 41216
#define O_VM 0
#define O_VV 4096
#define O_P  8320
#define O_P2 24960

__global__ __launch_bounds__(256) void attn_kernel()
{
    extern __shared__ float sm[];
    const int h  = blockIdx.y;
    const int q0 = blockIdx.x * 64;
    const int tid = threadIdx.x;
    const int tx = tid & 15, ty = tid >> 4;

    // ---- load q-side ([d][q], folded signs), k-side features ([d][k]) ----
    #pragma unroll
    for (int u = 0; u < 4; u++) {
        int idx = tid + u * 256;                 // 0..1023
        int q = idx >> 4, d4 = (idx & 15) << 2;
        float4 a = *(const float4*)(g_A  + (q0 + q) * D + h * DH + d4);
        float4 m = *(const float4*)(g_Qm + (q0 + q) * D + h * DH + d4);
        sm[O_AQ + (d4 + 0) * 65 + q] = a.x;
        sm[O_AQ + (d4 + 1) * 65 + q] = a.y;
        sm[O_AQ + (d4 + 2) * 65 + q] = a.z;
        sm[O_AQ + (d4 + 3) * 65 + q] = a.w;
        sm[O_QM + (d4 + 0) * 65 + q] = -m.x;
        sm[O_QM + (d4 + 1) * 65 + q] = -m.y;
        sm[O_QM + (d4 + 2) * 65 + q] = -m.z;
        sm[O_QM + (d4 + 3) * 65 + q] = -m.w;
    }
    #pragma unroll
    for (int u = 0; u < 16; u++) {
        int idx = tid + u * 256;                 // 0..4095
        int k = idx >> 4, d4 = (idx & 15) << 2;
        float4 f1 = *(const float4*)(g_F1 + k * D + h * DH + d4);
        float4 f2 = *(const float4*)(g_F2 + k * D + h * DH + d4);
        sm[O_F1 + (d4 + 0) * 257 + k] = f1.x;
        sm[O_F1 + (d4 + 1) * 257 + k] = f1.y;
        sm[O_F1 + (d4 + 2) * 257 + k] = f1.z;
        sm[O_F1 + (d4 + 3) * 257 + k] = f1.w;
        sm[O_F2 + (d4 + 0) * 257 + k] = f2.x;
        sm[O_F2 + (d4 + 1) * 257 + k] = f2.y;
        sm[O_F2 + (d4 + 2) * 257 + k] = f2.z;
        sm[O_F2 + (d4 + 3) * 257 + k] = f2.w;
    }
    if (tid < 256) sm[O_CK + tid] = g_Ck[h * L + tid];
    __syncthreads();

    // ---- scores: s[q, k] = 0.5*A.F1 - Qm.F2 (signs folded into smem) ----
    float s[4][16];
    #pragma unroll
    for (int i = 0; i < 4; i++)
        #pragma unroll
        for (int j = 0; j < 16; j++) s[i][j] = 0.0f;

    #pragma unroll 4
    for (int d = 0; d < 64; d++) {
        float a[4], qn[4];
        #pragma unroll
        for (int i = 0; i < 4; i++) {
            a[i]  = sm[O_AQ + d * 65 + ty * 4 + i];
            qn[i] = sm[O_QM + d * 65 + ty * 4 + i];
        }
        #pragma unroll
        for (int j = 0; j < 16; j++) {
            float f1 = sm[O_F1 + d * 257 + j * 16 + tx];
            float f2 = sm[O_F2 + d * 257 + j * 16 + tx];
            #pragma unroll
            for (int i = 0; i < 4; i++)
                s[i][j] += a[i] * f1 + qn[i] * f2;
        }
    }

    // add per-k bias, scale: score = -(kl)/8.  per-q terms cancel in softmax.
    #pragma unroll
    for (int j = 0; j < 16; j++) {
        float ck = sm[O_CK + j * 16 + tx];
        #pragma unroll
        for (int i = 0; i < 4; i++)
            s[i][j] = -0.125f * (s[i][j] + ck);
    }

    // ---- softmax over k (16 lanes x 16 regs per row) ----
    float rinv[4];
    #pragma unroll
    for (int i = 0; i < 4; i++) {
        float m = s[i][0];
        #pragma unroll
        for (int j = 1; j < 16; j++) m = fmaxf(m, s[i][j]);
        #pragma unroll
        for (int off = 8; off; off >>= 1)
            m = fmaxf(m, __shfl_xor_sync(0xffffffffu, m, off));
        float sum = 0.0f;
        #pragma unroll
        for (int j = 0; j < 16; j++) {
            float e = __expf(s[i][j] - m);
            s[i][j] = e;
            sum += e;
        }
        #pragma unroll
        for (int off = 8; off; off >>= 1)
            sum += __shfl_xor_sync(0xffffffffu, sum, off);
        rinv[i] = 1.0f / sum;
    }

    __syncthreads();   // all phase-1 smem reads complete

    // ---- write normalized attn and attn^2 ([k][q], padded 65) ----
    #pragma unroll
    for (int j = 0; j < 16; j++) {
        int k = j * 16 + tx;
        #pragma unroll
        for (int i = 0; i < 4; i++) {
            int q = ty * 4 + i;
            float pn = s[i][j] * rinv[i];
            sm[O_P  + k * 65 + q] = pn;
            sm[O_P2 + k * 65 + q] = pn * pn;
        }
    }

    // ---- PV: out = attn @ Vm, attn^2 @ Vv  (k-chunks of 64) ----
    float om[4][4], ov[4][4];
    #pragma unroll
    for (int i = 0; i < 4; i++)
        #pragma unroll
        for (int r = 0; r < 4; r++) { om[i][r] = 0.0f; ov[i][r] = 0.0f; }

    for (int kb = 0; kb < 4; kb++) {
        #pragma unroll
        for (int u = 0; u < 4; u++) {
            int idx = tid + u * 256;
            int r = idx >> 4, d4 = (idx & 15) << 2;
            *(float4*)&sm[O_VM + r * 64 + d4] =
                *(const float4*)(g_Vm + (kb * 64 + r) * D + h * DH + d4);
            *(float4*)&sm[O_VV + r * 64 + d4] =
                *(const float4*)(g_Vv + (kb * 64 + r) * D + h * DH + d4);
        }
        __syncthreads();
        #pragma unroll 4
        for (int kk = 0; kk < 64; kk++) {
            int k = kb * 64 + kk;
            float pm[4], pv[4];
            #pragma unroll
            for (int i = 0; i < 4; i++) {
                pm[i] = sm[O_P  + k * 65 + ty * 4 + i];
                pv[i] = sm[O_P2 + k * 65 + ty * 4 + i];
            }
            float4 vm = *(const float4*)&sm[O_VM + kk * 64 + tx * 4];
            float4 vv = *(const float4*)&sm[O_VV + kk * 64 + tx * 4];
            #pragma unroll
            for (int i = 0; i < 4; i++) {
                om[i][0] += pm[i] * vm.x; om[i][1] += pm[i] * vm.y;
                om[i][2] += pm[i] * vm.z; om[i][3] += pm[i] * vm.w;
                ov[i][0] += pv[i] * vv.x; ov[i][1] += pv[i] * vv.y;
                ov[i][2] += pv[i] * vv.z; ov[i][3] += pv[i] * vv.w;
            }
        }
        if (kb < 3) __syncthreads();
    }

    #pragma unroll
    for (int i = 0; i < 4; i++) {
        int q = q0 + ty * 4 + i;
        *(float4*)(g_Om + q * D + h * DH + tx * 4) =
            make_float4(om[i][0], om[i][1], om[i][2], om[i][3]);
        *(float4*)(g_Ov + q * D + h * DH + tx * 4) =
            make_float4(ov[i][0], ov[i][1], ov[i][2], ov[i][3]);
    }
}

// ---------------- kernel 4: output GEMMs ----------------
__global__ __launch_bounds__(256) void out_gemm_kernel(
    const float* wom, const float* bom, const float* wov, const float* bov,
    float* out)
{
    int bm = blockIdx.y * 128, bn = blockIdx.x * 128;
    if (blockIdx.z == 0)
        sgemm_tile(g_Om, wom, bom, out, bm, bn, false);
    else
        sgemm_tile(g_Ov, wov, bov, out + L * D, bm, bn, true);
}

// ---------------- launch ----------------
extern "C" void kernel_launch(void* const* d_in, const int* in_sizes, int n_in,
                              void* d_out, int out_size)
{
    const float* mu  = (const float*)d_in[0];
    const float* var = (const float*)d_in[1];
    const float* wqm = (const float*)d_in[2],  * bqm = (const float*)d_in[3];
    const float* wqv = (const float*)d_in[4],  * bqv = (const float*)d_in[5];
    const float* wkm = (const float*)d_in[6],  * bkm = (const float*)d_in[7];
    const float* wkv = (const float*)d_in[8],  * bkv = (const float*)d_in[9];
    const float* wvm = (const float*)d_in[10], * bvm = (const float*)d_in[11];
    const float* wvv = (const float*)d_in[12], * bvv = (const float*)d_in[13];
    const float* wom = (const float*)d_in[14], * bom = (const float*)d_in[15];
    const float* wov = (const float*)d_in[16], * bov = (const float*)d_in[17];
    float* out = (float*)d_out;

    cudaFuncSetAttribute(attn_kernel, cudaFuncAttributeMaxDynamicSharedMemorySize,
                         ATTN_SMEM_FLOATS * 4);

    dim3 g1(8, 2, 6);
    qkv_gemm_kernel<<<g1, 256>>>(mu, var, wqm, bqm, wqv, bqv,
                                 wkm, bkm, wkv, bkv, wvm, bvm, wvv, bvv);
    prep_kernel<<<512, 256>>>();
    attn_kernel<<<dim3(4, 16), 256, ATTN_SMEM_FLOATS * 4>>>();
    dim3 g2(8, 2, 2);
    out_gemm_kernel<<<g2, 256>>>(wom, bom, wov, bov, out);
}